// round 2
// baseline (speedup 1.0000x reference)
#include <cuda_runtime.h>
#include <math_constants.h>

// Problem constants
#define SB   16          // batch
#define SS   577         // seq
#define DD   768         // hidden
#define HH   12          // heads
#define HD   64          // head dim
#define MTOT (SB*SS)     // 9232 rows for projection GEMMs

// Scratch (device globals: no allocation allowed)
__device__ float g_q[(size_t)SB*HH*SS*HD];
__device__ float g_k[(size_t)SB*HH*SS*HD];
__device__ float g_v[(size_t)SB*HH*SS*HD];
__device__ float g_bias[(size_t)HH*SS*SS];

// ---------------------------------------------------------------------------
// 1) Precompute bias[h][q][k] = table[idx[q*S+k]*H + h]
// ---------------------------------------------------------------------------
__global__ __launch_bounds__(256) void bias_kernel(const float* __restrict__ table,
                                                   const int* __restrict__ idx)
{
    int e = blockIdx.x * 256 + threadIdx.x;
    if (e >= SS * SS) return;
    int i = idx[e];
    #pragma unroll
    for (int h = 0; h < HH; h++)
        g_bias[(size_t)h * SS * SS + e] = table[i * HH + h];
}

// ---------------------------------------------------------------------------
// 2) Projection GEMM: out[b,h,s,d] = (X @ W + bias) * scale
//    blockIdx.z: 0 = Q (bias bq, scale 1/8), 1 = K (no bias), 2 = V (bias bv)
//    BM=64, BN=64, BK=16; 256 threads, 4x4 per thread.
// ---------------------------------------------------------------------------
__global__ __launch_bounds__(256) void proj_kernel(
    const float* __restrict__ X,
    const float* __restrict__ Wq, const float* __restrict__ bq,
    const float* __restrict__ Wk,
    const float* __restrict__ Wv, const float* __restrict__ bv)
{
    __shared__ float As[16][68];   // [k][m], padded (float4-aligned rows)
    __shared__ float Bs[16][64];   // [k][n]

    const int which = blockIdx.z;
    const float* W    = (which == 0) ? Wq : (which == 1) ? Wk : Wv;
    const float* bias = (which == 0) ? bq : (which == 2) ? bv : nullptr;
    const float scale = (which == 0) ? 0.125f : 1.0f;   // 1/sqrt(64)
    float* out = (which == 0) ? g_q : (which == 1) ? g_k : g_v;

    const int tid = threadIdx.x;
    const int tx = tid & 15, ty = tid >> 4;
    const int n0 = blockIdx.x * 64;
    const int m0 = blockIdx.y * 64;

    float acc[4][4] = {};

    for (int k0 = 0; k0 < DD; k0 += 16) {
        // load A tile (64 x 16), transposed into As[k][m]
        {
            int r = tid >> 2;           // 0..63 row within tile
            int c = (tid & 3) << 2;     // 0,4,8,12
            int m = m0 + r;
            float4 a = (m < MTOT) ? *(const float4*)&X[(size_t)m * DD + k0 + c]
                                  : make_float4(0.f, 0.f, 0.f, 0.f);
            As[c + 0][r] = a.x; As[c + 1][r] = a.y;
            As[c + 2][r] = a.z; As[c + 3][r] = a.w;
        }
        // load B tile (16 x 64)
        {
            int r = tid >> 4;
            int c = (tid & 15) << 2;
            *(float4*)&Bs[r][c] = *(const float4*)&W[(size_t)(k0 + r) * DD + n0 + c];
        }
        __syncthreads();
        #pragma unroll
        for (int kk = 0; kk < 16; kk++) {
            float4 a4 = *(float4*)&As[kk][ty << 2];
            float4 b4 = *(float4*)&Bs[kk][tx << 2];
            float av[4] = {a4.x, a4.y, a4.z, a4.w};
            float bv4[4] = {b4.x, b4.y, b4.z, b4.w};
            #pragma unroll
            for (int i = 0; i < 4; i++)
                #pragma unroll
                for (int j = 0; j < 4; j++)
                    acc[i][j] += av[i] * bv4[j];
        }
        __syncthreads();
    }

    // epilogue: this block's 64 cols are exactly one head (n0 % 64 == 0)
    const int h = n0 / HD;
    float badd[4];
    #pragma unroll
    for (int j = 0; j < 4; j++)
        badd[j] = bias ? bias[n0 + (tx << 2) + j] : 0.0f;

    #pragma unroll
    for (int i = 0; i < 4; i++) {
        int m = m0 + (ty << 2) + i;
        if (m >= MTOT) continue;
        int b = m / SS, s = m % SS;
        float4 o;
        o.x = (acc[i][0] + badd[0]) * scale;
        o.y = (acc[i][1] + badd[1]) * scale;
        o.z = (acc[i][2] + badd[2]) * scale;
        o.w = (acc[i][3] + badd[3]) * scale;
        *(float4*)&out[(((size_t)(b * HH + h) * SS + s) * HD) + (tx << 2)] = o;
    }
}

// ---------------------------------------------------------------------------
// 3) Flash attention: per (q-tile, b*h) block.
//    BQ=64, BK=32. 256 threads (16x16): each thread 4 q-rows;
//    S phase: 2 k-cols/thread; PV phase: 4 d-cols/thread.
// ---------------------------------------------------------------------------
__global__ __launch_bounds__(256) void attn_kernel(float* __restrict__ out)
{
    __shared__ float q_s[64][65];
    __shared__ float k_s[32][65];
    __shared__ float v_s[32][64];
    __shared__ float p_s[64][33];

    const int tid = threadIdx.x;
    const int tx = tid & 15, ty = tid >> 4;
    const int q0 = blockIdx.x * 64;
    const int bh = blockIdx.y;
    const int b = bh / HH, h = bh % HH;

    const float* qg = g_q + (size_t)bh * SS * HD;
    const float* kg = g_k + (size_t)bh * SS * HD;
    const float* vg = g_v + (size_t)bh * SS * HD;
    const float* biasg = g_bias + (size_t)h * SS * SS;

    // load Q tile (64 x 64) — zero-fill OOB rows
    for (int e = tid; e < 64 * 16; e += 256) {
        int r = e >> 4, c = (e & 15) << 2;
        int srow = q0 + r;
        float4 qv = (srow < SS) ? *(const float4*)&qg[(size_t)srow * HD + c]
                                : make_float4(0.f, 0.f, 0.f, 0.f);
        q_s[r][c] = qv.x; q_s[r][c + 1] = qv.y;
        q_s[r][c + 2] = qv.z; q_s[r][c + 3] = qv.w;
    }

    float m_r[4], l_r[4], o_acc[4][4];
    #pragma unroll
    for (int i = 0; i < 4; i++) {
        m_r[i] = -CUDART_INF_F; l_r[i] = 0.0f;
        #pragma unroll
        for (int j = 0; j < 4; j++) o_acc[i][j] = 0.0f;
    }

    const int NKT = (SS + 31) / 32;  // 19
    for (int jt = 0; jt < NKT; jt++) {
        const int j0 = jt * 32;
        __syncthreads();   // prev PV done (also covers initial Q load)

        // load K/V tiles (32 x 64)
        for (int e = tid; e < 32 * 16; e += 256) {
            int r = e >> 4, c = (e & 15) << 2;
            int srow = j0 + r;
            if (srow < SS) {
                float4 kv = *(const float4*)&kg[(size_t)srow * HD + c];
                k_s[r][c] = kv.x; k_s[r][c + 1] = kv.y;
                k_s[r][c + 2] = kv.z; k_s[r][c + 3] = kv.w;
                *(float4*)&v_s[r][c] = *(const float4*)&vg[(size_t)srow * HD + c];
            } else {
                k_s[r][c] = k_s[r][c + 1] = k_s[r][c + 2] = k_s[r][c + 3] = 0.0f;
                *(float4*)&v_s[r][c] = make_float4(0.f, 0.f, 0.f, 0.f);
            }
        }
        __syncthreads();

        // S = Q @ K^T (each thread: 4 q-rows x 2 k-cols)
        float sacc[4][2] = {};
        #pragma unroll 8
        for (int d = 0; d < 64; d++) {
            float a0 = q_s[(ty << 2) + 0][d];
            float a1 = q_s[(ty << 2) + 1][d];
            float a2 = q_s[(ty << 2) + 2][d];
            float a3 = q_s[(ty << 2) + 3][d];
            float c0 = k_s[(tx << 1) + 0][d];
            float c1 = k_s[(tx << 1) + 1][d];
            sacc[0][0] += a0 * c0; sacc[0][1] += a0 * c1;
            sacc[1][0] += a1 * c0; sacc[1][1] += a1 * c1;
            sacc[2][0] += a2 * c0; sacc[2][1] += a2 * c1;
            sacc[3][0] += a3 * c0; sacc[3][1] += a3 * c1;
        }

        // bias + mask
        #pragma unroll
        for (int i = 0; i < 4; i++) {
            int qrow = q0 + (ty << 2) + i;
            #pragma unroll
            for (int j = 0; j < 2; j++) {
                int kcol = j0 + (tx << 1) + j;
                if (kcol < SS) {
                    if (qrow < SS)
                        sacc[i][j] += __ldg(&biasg[(size_t)qrow * SS + kcol]);
                } else {
                    sacc[i][j] = -CUDART_INF_F;
                }
            }
        }

        // online softmax (row = 16 lanes within half-warp)
        #pragma unroll
        for (int i = 0; i < 4; i++) {
            float mx = fmaxf(sacc[i][0], sacc[i][1]);
            mx = fmaxf(mx, __shfl_xor_sync(0xffffffffu, mx, 1));
            mx = fmaxf(mx, __shfl_xor_sync(0xffffffffu, mx, 2));
            mx = fmaxf(mx, __shfl_xor_sync(0xffffffffu, mx, 4));
            mx = fmaxf(mx, __shfl_xor_sync(0xffffffffu, mx, 8));
            float m_new = fmaxf(m_r[i], mx);
            float corr = __expf(m_r[i] - m_new);   // first tile: exp(-inf)=0
            m_r[i] = m_new;
            float p0 = __expf(sacc[i][0] - m_new); // masked: exp(-inf)=0
            float p1 = __expf(sacc[i][1] - m_new);
            float rs = p0 + p1;
            rs += __shfl_xor_sync(0xffffffffu, rs, 1);
            rs += __shfl_xor_sync(0xffffffffu, rs, 2);
            rs += __shfl_xor_sync(0xffffffffu, rs, 4);
            rs += __shfl_xor_sync(0xffffffffu, rs, 8);
            l_r[i] = l_r[i] * corr + rs;
            #pragma unroll
            for (int j = 0; j < 4; j++) o_acc[i][j] *= corr;
            p_s[(ty << 2) + i][(tx << 1) + 0] = p0;
            p_s[(ty << 2) + i][(tx << 1) + 1] = p1;
        }
        __syncthreads();

        // O += P @ V (each thread: 4 q-rows x 4 d-cols)
        #pragma unroll 8
        for (int kk = 0; kk < 32; kk++) {
            float p0 = p_s[(ty << 2) + 0][kk];
            float p1 = p_s[(ty << 2) + 1][kk];
            float p2 = p_s[(ty << 2) + 2][kk];
            float p3 = p_s[(ty << 2) + 3][kk];
            float4 vv = *(float4*)&v_s[kk][tx << 2];
            o_acc[0][0] += p0 * vv.x; o_acc[0][1] += p0 * vv.y;
            o_acc[0][2] += p0 * vv.z; o_acc[0][3] += p0 * vv.w;
            o_acc[1][0] += p1 * vv.x; o_acc[1][1] += p1 * vv.y;
            o_acc[1][2] += p1 * vv.z; o_acc[1][3] += p1 * vv.w;
            o_acc[2][0] += p2 * vv.x; o_acc[2][1] += p2 * vv.y;
            o_acc[2][2] += p2 * vv.z; o_acc[2][3] += p2 * vv.w;
            o_acc[3][0] += p3 * vv.x; o_acc[3][1] += p3 * vv.y;
            o_acc[3][2] += p3 * vv.z; o_acc[3][3] += p3 * vv.w;
        }
    }

    // write out: [B,S,D] with d-col = h*64 + tx*4 + j
    #pragma unroll
    for (int i = 0; i < 4; i++) {
        int qrow = q0 + (ty << 2) + i;
        if (qrow >= SS) continue;
        float inv = 1.0f / l_r[i];
        float4 o;
        o.x = o_acc[i][0] * inv; o.y = o_acc[i][1] * inv;
        o.z = o_acc[i][2] * inv; o.w = o_acc[i][3] * inv;
        *(float4*)&out[((size_t)b * SS + qrow) * DD + h * HD + (tx << 2)] = o;
    }
}

// ---------------------------------------------------------------------------
extern "C" void kernel_launch(void* const* d_in, const int* in_sizes, int n_in,
                              void* d_out, int out_size)
{
    const float* X     = (const float*)d_in[0];
    const float* Wq    = (const float*)d_in[1];
    const float* bq    = (const float*)d_in[2];
    const float* Wk    = (const float*)d_in[3];
    const float* Wv    = (const float*)d_in[4];
    const float* bv    = (const float*)d_in[5];
    const float* table = (const float*)d_in[6];
    const int*   idx   = (const int*)d_in[7];
    float* out = (float*)d_out;

    // bias precompute
    bias_kernel<<<(SS * SS + 255) / 256, 256>>>(table, idx);

    // Q/K/V projections: grid (N/64, ceil(M/64), 3)
    dim3 pg(DD / 64, (MTOT + 63) / 64, 3);
    proj_kernel<<<pg, 256>>>(X, Wq, bq, Wk, Wv, bv);

    // flash attention: grid (q-tiles, B*H)
    dim3 ag((SS + 63) / 64, SB * HH);
    attn_kernel<<<ag, 256>>>(out);
}

// round 7
// speedup vs baseline: 1.5070x; 1.5070x over previous
#include <cuda_runtime.h>
#include <math_constants.h>
#include <cstdint>

#define SB 16
#define SS 577
#define DD 768
#define HH 12
#define HD 64
#define MTOT (SB*SS)

// projection GEMM tiling
#define BM 128
#define BN 128
#define BK 32
#define NKC (DD/BK)      // 24
#define ASTR 36          // padded smem row stride (floats)

__device__ float g_q[(size_t)SB*HH*SS*HD];
__device__ float g_k[(size_t)SB*HH*SS*HD];
__device__ float g_v[(size_t)SB*HH*SS*HD];
__device__ float g_wt[(size_t)3*DD*DD];
__device__ float g_bias[(size_t)HH*SS*SS];

typedef unsigned long long u64t;

__device__ __forceinline__ uint32_t tf32r(float x){
    uint32_t o; asm("cvt.rna.tf32.f32 %0, %1;" : "=r"(o) : "f"(x));
    return o;
}
__device__ __forceinline__ u64t f2fma(u64t a, u64t b, u64t c){
    u64t d; asm("fma.rn.f32x2 %0, %1, %2, %3;" : "=l"(d) : "l"(a), "l"(b), "l"(c)); return d;
}
__device__ __forceinline__ u64t pack2(float x, float y){
    u64t d; asm("mov.b64 %0, {%1,%2};" : "=l"(d) : "r"(__float_as_uint(x)), "r"(__float_as_uint(y))); return d;
}
__device__ __forceinline__ float hsum2(u64t a){
    uint32_t l, h; asm("mov.b64 {%0,%1}, %2;" : "=r"(l), "=r"(h) : "l"(a));
    return __uint_as_float(l) + __uint_as_float(h);
}
__device__ __forceinline__ void mma_tf32(float* c, const uint32_t* a, const uint32_t* b){
    asm volatile(
        "mma.sync.aligned.m16n8k8.row.col.f32.tf32.tf32.f32 "
        "{%0,%1,%2,%3}, {%4,%5,%6,%7}, {%8,%9}, {%0,%1,%2,%3};"
        : "+f"(c[0]), "+f"(c[1]), "+f"(c[2]), "+f"(c[3])
        : "r"(a[0]), "r"(a[1]), "r"(a[2]), "r"(a[3]), "r"(b[0]), "r"(b[1]));
}

// ---------------- 1) bias gather ----------------
__global__ __launch_bounds__(256) void bias_kernel(const float* __restrict__ table,
                                                   const int* __restrict__ idx)
{
    int e = blockIdx.x * 256 + threadIdx.x;
    if (e >= SS * SS) return;
    int i = idx[e];
    #pragma unroll
    for (int h = 0; h < HH; h++)
        g_bias[(size_t)h * SS * SS + e] = table[i * HH + h];
}

// ---------------- 2) weight transpose: g_wt[g][n][k] = W[k][n] ----------------
__global__ void transpose_w(const float* __restrict__ Wq,
                            const float* __restrict__ Wk,
                            const float* __restrict__ Wv)
{
    __shared__ float t[32][33];
    int g = blockIdx.z;
    const float* W = (g == 0) ? Wq : (g == 1) ? Wk : Wv;
    int k0 = blockIdx.x * 32, n0 = blockIdx.y * 32;
    int tx = threadIdx.x, ty = threadIdx.y;
    #pragma unroll
    for (int i = 0; i < 32; i += 8)
        t[ty + i][tx] = W[(size_t)(k0 + ty + i) * DD + n0 + tx];
    __syncthreads();
    #pragma unroll
    for (int i = 0; i < 32; i += 8)
        g_wt[(size_t)g * DD * DD + (size_t)(n0 + ty + i) * DD + k0 + tx] = t[tx][ty + i];
}

// ---------------- 3) projection via mma.sync tf32 ----------------
// C[M,768] = X @ W (+bias)*scale, written into [b,h,s,d] layout.
// 256 threads = 8 warps (2x4). Warp tile 64x32. Double-buffered BK=32.
#define PROJ_SMEM (2u * (BM + BN) * ASTR * 4u)   // 73728 B

__global__ __launch_bounds__(256) void proj_mma_kernel(
    const float* __restrict__ X,
    const float* __restrict__ bq, const float* __restrict__ bv)
{
    extern __shared__ float smf[];
    float* As = smf;                       // [2][BM][ASTR]
    float* Bs = smf + 2 * BM * ASTR;       // [2][BN][ASTR]

    const int tid = threadIdx.x;
    const int wid = tid >> 5, lane = tid & 31;
    const int wm = (wid >> 2) * 64;        // warp m offset (0,64)
    const int wn = (wid & 3) * 32;         // warp n offset (0..96)
    const int g = lane >> 2, tg = lane & 3;

    const int m0 = blockIdx.x * BM;
    const int n0 = blockIdx.y * BN;
    const int which = blockIdx.z;
    const float* Wt   = g_wt + (size_t)which * DD * DD;
    float* out        = (which == 0) ? g_q : (which == 1) ? g_k : g_v;
    const float* badd = (which == 0) ? bq : (which == 2) ? bv : nullptr;
    const float scl   = (which == 0) ? 0.125f : 1.0f;

    // per-thread staging slots: 4 float4 for A, 4 for B
    const int ar = tid >> 1;                    // 0..127 row
    const int ac = (tid & 1) << 4;              // 0 or 16 (floats)
    float4 ra[4], rb[4];

    #define LOAD_CHUNK(kc)                                                          \
    {                                                                               \
        int kb = (kc) * BK;                                                         \
        _Pragma("unroll")                                                           \
        for (int i = 0; i < 4; i++) {                                               \
            int m = m0 + ar;                                                        \
            ra[i] = (m < MTOT) ? *(const float4*)&X[(size_t)m * DD + kb + ac + i*4] \
                               : make_float4(0.f,0.f,0.f,0.f);                      \
            rb[i] = *(const float4*)&Wt[(size_t)(n0 + ar) * DD + kb + ac + i*4];    \
        }                                                                           \
    }
    #define STORE_CHUNK(buf)                                                        \
    {                                                                               \
        float* ap = As + (buf) * BM * ASTR + ar * ASTR + ac;                        \
        float* bp = Bs + (buf) * BN * ASTR + ar * ASTR + ac;                        \
        _Pragma("unroll")                                                           \
        for (int i = 0; i < 4; i++) {                                               \
            float4 va = ra[i], vb = rb[i];                                          \
            va.x = __uint_as_float(tf32r(va.x)); va.y = __uint_as_float(tf32r(va.y));\
            va.z = __uint_as_float(tf32r(va.z)); va.w = __uint_as_float(tf32r(va.w));\
            vb.x = __uint_as_float(tf32r(vb.x)); vb.y = __uint_as_float(tf32r(vb.y));\
            vb.z = __uint_as_float(tf32r(vb.z)); vb.w = __uint_as_float(tf32r(vb.w));\
            *(float4*)&ap[i*4] = va;                                                \
            *(float4*)&bp[i*4] = vb;                                                \
        }                                                                           \
    }

    float acc[4][4][4] = {};   // [mf][nf][reg]

    LOAD_CHUNK(0);
    STORE_CHUNK(0);
    __syncthreads();

    for (int kc = 0; kc < NKC; kc++) {
        const int buf = kc & 1;
        if (kc < NKC - 1) LOAD_CHUNK(kc + 1);

        const float* ab = As + buf * BM * ASTR;
        const float* bb = Bs + buf * BN * ASTR;
        #pragma unroll
        for (int ks = 0; ks < 4; ks++) {
            const int k8 = ks * 8;
            uint32_t af[4][4], bf[4][2];
            #pragma unroll
            for (int mf = 0; mf < 4; mf++) {
                const float* p = ab + (wm + mf * 16 + g) * ASTR + k8 + tg;
                af[mf][0] = __float_as_uint(p[0]);
                af[mf][2] = __float_as_uint(p[4]);
                af[mf][1] = __float_as_uint(p[8 * ASTR]);
                af[mf][3] = __float_as_uint(p[8 * ASTR + 4]);
            }
            #pragma unroll
            for (int nf = 0; nf < 4; nf++) {
                const float* p = bb + (wn + nf * 8 + g) * ASTR + k8 + tg;
                bf[nf][0] = __float_as_uint(p[0]);
                bf[nf][1] = __float_as_uint(p[4]);
            }
            #pragma unroll
            for (int mf = 0; mf < 4; mf++)
                #pragma unroll
                for (int nf = 0; nf < 4; nf++)
                    mma_tf32(acc[mf][nf], af[mf], bf[nf]);
        }

        if (kc < NKC - 1) STORE_CHUNK((kc + 1) & 1);
        __syncthreads();
    }

    // epilogue: scatter float2 stores into [b,h,s,64]
    #pragma unroll
    for (int mf = 0; mf < 4; mf++) {
        #pragma unroll
        for (int half = 0; half < 2; half++) {
            int m = m0 + wm + mf * 16 + g + half * 8;
            if (m >= MTOT) continue;
            int b = m / SS, s = m - b * SS;
            #pragma unroll
            for (int nf = 0; nf < 4; nf++) {
                int n = n0 + wn + nf * 8 + tg * 2;
                int h = n >> 6, d = n & 63;
                float c0 = acc[mf][nf][half * 2 + 0];
                float c1 = acc[mf][nf][half * 2 + 1];
                if (badd) { c0 += badd[n]; c1 += badd[n + 1]; }
                float2 v = make_float2(c0 * scl, c1 * scl);
                *(float2*)&out[((size_t)(b * HH + h) * SS + s) * HD + d] = v;
            }
        }
    }
}

// ---------------- 4) flash attention, packed f32x2 ----------------
__global__ __launch_bounds__(256) void attn_kernel(float* __restrict__ out)
{
    __shared__ __align__(16) float q_s[64][66];
    __shared__ __align__(16) float k_s[32][66];
    __shared__ __align__(16) float vT[64][34];
    __shared__ __align__(16) float p_s[64][34];

    const int tid = threadIdx.x;
    const int tx = tid & 15, ty = tid >> 4;
    const int q0 = blockIdx.x * 64;
    const int bh = blockIdx.y;              // h*16 + b (bias L2 reuse)
    const int h = bh >> 4, b = bh & 15;
    const int qr = ty << 2;

    const float* qg = g_q + (size_t)(b * HH + h) * SS * HD;
    const float* kg = g_k + (size_t)(b * HH + h) * SS * HD;
    const float* vg = g_v + (size_t)(b * HH + h) * SS * HD;
    const float* biasg = g_bias + (size_t)h * SS * SS;

    #pragma unroll
    for (int i = 0; i < 4; i++) {
        int u = tid + i * 256;
        int r = u >> 4, c = (u & 15) << 2;
        int srow = q0 + r;
        float4 qv = (srow < SS) ? *(const float4*)&qg[(size_t)srow * HD + c]
                                : make_float4(0.f, 0.f, 0.f, 0.f);
        *(float2*)&q_s[r][c]     = make_float2(qv.x, qv.y);
        *(float2*)&q_s[r][c + 2] = make_float2(qv.z, qv.w);
    }

    float m_r[4], l_r[4];
    u64t o2[4][4];
    #pragma unroll
    for (int i = 0; i < 4; i++) {
        m_r[i] = -CUDART_INF_F; l_r[i] = 0.0f;
        #pragma unroll
        for (int j = 0; j < 4; j++) o2[i][j] = 0ull;
    }

    const int NKT = (SS + 31) / 32;
    for (int jt = 0; jt < NKT; jt++) {
        const int j0 = jt * 32;
        __syncthreads();
        #pragma unroll
        for (int i = 0; i < 2; i++) {
            int u = tid + i * 256;
            int r = u >> 4, c = (u & 15) << 2;
            int srow = j0 + r;
            float4 kv, vv;
            if (srow < SS) {
                kv = *(const float4*)&kg[(size_t)srow * HD + c];
                vv = *(const float4*)&vg[(size_t)srow * HD + c];
            } else {
                kv = make_float4(0.f,0.f,0.f,0.f); vv = kv;
            }
            *(float2*)&k_s[r][c]     = make_float2(kv.x, kv.y);
            *(float2*)&k_s[r][c + 2] = make_float2(kv.z, kv.w);
            vT[c + 0][r] = vv.x; vT[c + 1][r] = vv.y;
            vT[c + 2][r] = vv.z; vT[c + 3][r] = vv.w;
        }
        __syncthreads();

        // S = Q K^T : pairs along d
        u64t s2[4][2] = {};
        #pragma unroll
        for (int d = 0; d < 64; d += 2) {
            u64t k0v = *(const u64t*)&k_s[tx][d];
            u64t k1v = *(const u64t*)&k_s[tx + 16][d];
            #pragma unroll
            for (int i = 0; i < 4; i++) {
                u64t qv = *(const u64t*)&q_s[qr + i][d];
                s2[i][0] = f2fma(qv, k0v, s2[i][0]);
                s2[i][1] = f2fma(qv, k1v, s2[i][1]);
            }
        }
        float sacc[4][2];
        #pragma unroll
        for (int i = 0; i < 4; i++) {
            sacc[i][0] = hsum2(s2[i][0]);
            sacc[i][1] = hsum2(s2[i][1]);
        }
        #pragma unroll
        for (int i = 0; i < 4; i++) {
            int qrow = q0 + qr + i;
            #pragma unroll
            for (int j = 0; j < 2; j++) {
                int kcol = j0 + tx + 16 * j;
                if (kcol < SS) {
                    if (qrow < SS) sacc[i][j] += __ldg(&biasg[(size_t)qrow * SS + kcol]);
                } else sacc[i][j] = -CUDART_INF_F;
            }
        }
        #pragma unroll
        for (int i = 0; i < 4; i++) {
            float mx = fmaxf(sacc[i][0], sacc[i][1]);
            mx = fmaxf(mx, __shfl_xor_sync(0xffffffffu, mx, 1));
            mx = fmaxf(mx, __shfl_xor_sync(0xffffffffu, mx, 2));
            mx = fmaxf(mx, __shfl_xor_sync(0xffffffffu, mx, 4));
            mx = fmaxf(mx, __shfl_xor_sync(0xffffffffu, mx, 8));
            float m_new = fmaxf(m_r[i], mx);
            float corr = __expf(m_r[i] - m_new);
            m_r[i] = m_new;
            float p0 = __expf(sacc[i][0] - m_new);
            float p1 = __expf(sacc[i][1] - m_new);
            float rs = p0 + p1;
            rs += __shfl_xor_sync(0xffffffffu, rs, 1);
            rs += __shfl_xor_sync(0xffffffffu, rs, 2);
            rs += __shfl_xor_sync(0xffffffffu, rs, 4);
            rs += __shfl_xor_sync(0xffffffffu, rs, 8);
            l_r[i] = l_r[i] * corr + rs;
            u64t c2 = pack2(corr, corr);
            #pragma unroll
            for (int j = 0; j < 4; j++)
                o2[i][j] = f2fma(o2[i][j], c2, 0ull);
            p_s[qr + i][tx]      = p0;
            p_s[qr + i][tx + 16] = p1;
        }
        __syncthreads();

        // O += P V : pairs along k
        #pragma unroll
        for (int kk = 0; kk < 32; kk += 2) {
            u64t p2[4];
            #pragma unroll
            for (int i = 0; i < 4; i++)
                p2[i] = *(const u64t*)&p_s[qr + i][kk];
            #pragma unroll
            for (int j = 0; j < 4; j++) {
                u64t vv = *(const u64t*)&vT[tx + 16 * j][kk];
                #pragma unroll
                for (int i = 0; i < 4; i++)
                    o2[i][j] = f2fma(p2[i], vv, o2[i][j]);
            }
        }
    }

    #pragma unroll
    for (int i = 0; i < 4; i++) {
        int qrow = q0 + qr + i;
        if (qrow >= SS) continue;
        float inv = 1.0f / l_r[i];
        float* op = &out[((size_t)b * SS + qrow) * DD + h * HD];
        #pragma unroll
        for (int j = 0; j < 4; j++)
            op[tx + 16 * j] = hsum2(o2[i][j]) * inv;
    }
}

// ---------------------------------------------------------------------------
extern "C" void kernel_launch(void* const* d_in, const int* in_sizes, int n_in,
                              void* d_out, int out_size)
{
    const float* X     = (const float*)d_in[0];
    const float* Wq    = (const float*)d_in[1];
    const float* bq    = (const float*)d_in[2];
    const float* Wk    = (const float*)d_in[3];
    const float* Wv    = (const float*)d_in[4];
    const float* bv    = (const float*)d_in[5];
    const float* table = (const float*)d_in[6];
    const int*   idx   = (const int*)d_in[7];
    float* out = (float*)d_out;

    cudaFuncSetAttribute(proj_mma_kernel, cudaFuncAttributeMaxDynamicSharedMemorySize, (int)PROJ_SMEM);

    bias_kernel<<<(SS * SS + 255) / 256, 256>>>(table, idx);
    transpose_w<<<dim3(DD/32, DD/32, 3), dim3(32, 8)>>>(Wq, Wk, Wv);
    proj_mma_kernel<<<dim3((MTOT + BM - 1) / BM, DD / BN, 3), 256, PROJ_SMEM>>>(X, bq, bv);
    attn_kernel<<<dim3((SS + 63) / 64, SB * HH), 256>>>(out);
}

// round 8
// speedup vs baseline: 2.2558x; 1.4969x over previous
#include <cuda_runtime.h>
#include <math_constants.h>
#include <cstdint>

#define SB 16
#define SS 577
#define DD 768
#define HH 12
#define HD 64
#define MTOT (SB*SS)

// projection GEMM tiling
#define BM 128
#define BN 128
#define BK 32
#define NKC (DD/BK)      // 24
#define ASTR 36          // padded smem row stride (floats)

// attention tiling
#define KST 68           // K and P smem stride
#define VST 72           // V smem stride

__device__ float g_q[(size_t)SB*HH*SS*HD];
__device__ float g_k[(size_t)SB*HH*SS*HD];
__device__ float g_v[(size_t)SB*HH*SS*HD];
__device__ float g_wt[(size_t)3*DD*DD];
__device__ float g_bias[(size_t)HH*SS*SS];

__device__ __forceinline__ uint32_t tf32r(float x){
    uint32_t o; asm("cvt.rna.tf32.f32 %0, %1;" : "=r"(o) : "f"(x));
    return o;
}
__device__ __forceinline__ void mma_tf32(float* c, const uint32_t* a, const uint32_t* b){
    asm volatile(
        "mma.sync.aligned.m16n8k8.row.col.f32.tf32.tf32.f32 "
        "{%0,%1,%2,%3}, {%4,%5,%6,%7}, {%8,%9}, {%0,%1,%2,%3};"
        : "+f"(c[0]), "+f"(c[1]), "+f"(c[2]), "+f"(c[3])
        : "r"(a[0]), "r"(a[1]), "r"(a[2]), "r"(a[3]), "r"(b[0]), "r"(b[1]));
}

// ---------------- 1) bias gather ----------------
__global__ __launch_bounds__(256) void bias_kernel(const float* __restrict__ table,
                                                   const int* __restrict__ idx)
{
    int e = blockIdx.x * 256 + threadIdx.x;
    if (e >= SS * SS) return;
    int i = idx[e];
    #pragma unroll
    for (int h = 0; h < HH; h++)
        g_bias[(size_t)h * SS * SS + e] = table[i * HH + h];
}

// ---------------- 2) weight transpose: g_wt[g][n][k] = W[k][n] ----------------
__global__ void transpose_w(const float* __restrict__ Wq,
                            const float* __restrict__ Wk,
                            const float* __restrict__ Wv)
{
    __shared__ float t[32][33];
    int g = blockIdx.z;
    const float* W = (g == 0) ? Wq : (g == 1) ? Wk : Wv;
    int k0 = blockIdx.x * 32, n0 = blockIdx.y * 32;
    int tx = threadIdx.x, ty = threadIdx.y;
    #pragma unroll
    for (int i = 0; i < 32; i += 8)
        t[ty + i][tx] = W[(size_t)(k0 + ty + i) * DD + n0 + tx];
    __syncthreads();
    #pragma unroll
    for (int i = 0; i < 32; i += 8)
        g_wt[(size_t)g * DD * DD + (size_t)(n0 + ty + i) * DD + k0 + tx] = t[tx][ty + i];
}

// ---------------- 3) projection via mma.sync tf32 ----------------
#define PROJ_SMEM (2u * (BM + BN) * ASTR * 4u)

__global__ __launch_bounds__(256) void proj_mma_kernel(
    const float* __restrict__ X,
    const float* __restrict__ bq, const float* __restrict__ bv)
{
    extern __shared__ float smf[];
    float* As = smf;
    float* Bs = smf + 2 * BM * ASTR;

    const int tid = threadIdx.x;
    const int wid = tid >> 5, lane = tid & 31;
    const int wm = (wid >> 2) * 64;
    const int wn = (wid & 3) * 32;
    const int g = lane >> 2, tg = lane & 3;

    const int m0 = blockIdx.x * BM;
    const int n0 = blockIdx.y * BN;
    const int which = blockIdx.z;
    const float* Wt   = g_wt + (size_t)which * DD * DD;
    float* out        = (which == 0) ? g_q : (which == 1) ? g_k : g_v;
    const float* badd = (which == 0) ? bq : (which == 2) ? bv : nullptr;
    const float scl   = (which == 0) ? 0.125f : 1.0f;

    const int ar = tid >> 1;
    const int ac = (tid & 1) << 4;
    float4 ra[4], rb[4];

    #define LOAD_CHUNK(kc)                                                          \
    {                                                                               \
        int kb = (kc) * BK;                                                         \
        _Pragma("unroll")                                                           \
        for (int i = 0; i < 4; i++) {                                               \
            int m = m0 + ar;                                                        \
            ra[i] = (m < MTOT) ? *(const float4*)&X[(size_t)m * DD + kb + ac + i*4] \
                               : make_float4(0.f,0.f,0.f,0.f);                      \
            rb[i] = *(const float4*)&Wt[(size_t)(n0 + ar) * DD + kb + ac + i*4];    \
        }                                                                           \
    }
    #define STORE_CHUNK(buf)                                                        \
    {                                                                               \
        float* ap = As + (buf) * BM * ASTR + ar * ASTR + ac;                        \
        float* bp = Bs + (buf) * BN * ASTR + ar * ASTR + ac;                        \
        _Pragma("unroll")                                                           \
        for (int i = 0; i < 4; i++) {                                               \
            float4 va = ra[i], vb = rb[i];                                          \
            va.x = __uint_as_float(tf32r(va.x)); va.y = __uint_as_float(tf32r(va.y));\
            va.z = __uint_as_float(tf32r(va.z)); va.w = __uint_as_float(tf32r(va.w));\
            vb.x = __uint_as_float(tf32r(vb.x)); vb.y = __uint_as_float(tf32r(vb.y));\
            vb.z = __uint_as_float(tf32r(vb.z)); vb.w = __uint_as_float(tf32r(vb.w));\
            *(float4*)&ap[i*4] = va;                                                \
            *(float4*)&bp[i*4] = vb;                                                \
        }                                                                           \
    }

    float acc[4][4][4] = {};

    LOAD_CHUNK(0);
    STORE_CHUNK(0);
    __syncthreads();

    for (int kc = 0; kc < NKC; kc++) {
        const int buf = kc & 1;
        if (kc < NKC - 1) LOAD_CHUNK(kc + 1);

        const float* ab = As + buf * BM * ASTR;
        const float* bb = Bs + buf * BN * ASTR;
        #pragma unroll
        for (int ks = 0; ks < 4; ks++) {
            const int k8 = ks * 8;
            uint32_t af[4][4], bf[4][2];
            #pragma unroll
            for (int mf = 0; mf < 4; mf++) {
                const float* p = ab + (wm + mf * 16 + g) * ASTR + k8 + tg;
                af[mf][0] = __float_as_uint(p[0]);
                af[mf][2] = __float_as_uint(p[4]);
                af[mf][1] = __float_as_uint(p[8 * ASTR]);
                af[mf][3] = __float_as_uint(p[8 * ASTR + 4]);
            }
            #pragma unroll
            for (int nf = 0; nf < 4; nf++) {
                const float* p = bb + (wn + nf * 8 + g) * ASTR + k8 + tg;
                bf[nf][0] = __float_as_uint(p[0]);
                bf[nf][1] = __float_as_uint(p[4]);
            }
            #pragma unroll
            for (int mf = 0; mf < 4; mf++)
                #pragma unroll
                for (int nf = 0; nf < 4; nf++)
                    mma_tf32(acc[mf][nf], af[mf], bf[nf]);
        }

        if (kc < NKC - 1) STORE_CHUNK((kc + 1) & 1);
        __syncthreads();
    }

    // epilogue: tf32-rounded stores into [b,h,s,64] (attn consumes raw bits)
    #pragma unroll
    for (int mf = 0; mf < 4; mf++) {
        #pragma unroll
        for (int half = 0; half < 2; half++) {
            int m = m0 + wm + mf * 16 + g + half * 8;
            if (m >= MTOT) continue;
            int b = m / SS, s = m - b * SS;
            #pragma unroll
            for (int nf = 0; nf < 4; nf++) {
                int n = n0 + wn + nf * 8 + tg * 2;
                int h = n >> 6, d = n & 63;
                float c0 = acc[mf][nf][half * 2 + 0];
                float c1 = acc[mf][nf][half * 2 + 1];
                if (badd) { c0 += badd[n]; c1 += badd[n + 1]; }
                float2 v;
                v.x = __uint_as_float(tf32r(c0 * scl));
                v.y = __uint_as_float(tf32r(c1 * scl));
                *(float2*)&out[((size_t)(b * HH + h) * SS + s) * HD + d] = v;
            }
        }
    }
}

// ---------------- 4) flash attention via mma.sync tf32 ----------------
// Block: 64 q-rows, 4 warps (16 rows each), 128 threads. Keys streamed in
// 64-wide tiles. Q fragments register-resident.
#define ATTN_SMEM ((64*KST + 64*VST + 64*KST) * 4)   // 53248 B

__global__ __launch_bounds__(128) void attn_kernel(float* __restrict__ out)
{
    extern __shared__ float sh[];
    float* ks = sh;                    // [64][KST]
    float* vs = ks + 64 * KST;         // [64][VST]
    float* ps = vs + 64 * VST;         // [64][KST]

    const int tid = threadIdx.x;
    const int wq = tid >> 5;
    const int lane = tid & 31;
    const int g = lane >> 2, tg = lane & 3;
    const int q0 = blockIdx.x * 64;
    const int bh = blockIdx.y;                 // h*16 + b
    const int h = bh >> 4, b = bh & 15;

    const float* qg = g_q + (size_t)(b * HH + h) * SS * HD;
    const float* kg = g_k + (size_t)(b * HH + h) * SS * HD;
    const float* vg = g_v + (size_t)(b * HH + h) * SS * HD;
    const float* biasg = g_bias + (size_t)h * SS * SS;

    const int r0 = q0 + wq * 16 + g;           // rows for c0/c1
    const int r1 = r0 + 8;                     // rows for c2/c3

    // Q fragments (row-major A, m16k8 x 8 ksteps) — register resident
    uint32_t qf[8][4];
    #pragma unroll
    for (int kk = 0; kk < 8; kk++) {
        int c = kk * 8 + tg;
        qf[kk][0] = (r0 < SS) ? __float_as_uint(qg[(size_t)r0 * HD + c])     : 0u;
        qf[kk][1] = (r1 < SS) ? __float_as_uint(qg[(size_t)r1 * HD + c])     : 0u;
        qf[kk][2] = (r0 < SS) ? __float_as_uint(qg[(size_t)r0 * HD + c + 4]) : 0u;
        qf[kk][3] = (r1 < SS) ? __float_as_uint(qg[(size_t)r1 * HD + c + 4]) : 0u;
    }

    float oacc[8][4];
    #pragma unroll
    for (int nf = 0; nf < 8; nf++)
        #pragma unroll
        for (int r = 0; r < 4; r++) oacc[nf][r] = 0.0f;
    float m0r = -CUDART_INF_F, m1r = -CUDART_INF_F, l0r = 0.0f, l1r = 0.0f;

    #pragma unroll 1
    for (int jt = 0; jt < 10; jt++) {
        const int j0 = jt * 64;
        __syncthreads();
        // stage K and V tiles (coalesced, zero-fill OOB)
        #pragma unroll
        for (int i = 0; i < 8; i++) {
            int u = tid + i * 128;
            int r = u >> 4, c = (u & 15) << 2;
            int srow = j0 + r;
            float4 kv, vv;
            if (srow < SS) {
                kv = *(const float4*)&kg[(size_t)srow * HD + c];
                vv = *(const float4*)&vg[(size_t)srow * HD + c];
            } else {
                kv = make_float4(0.f, 0.f, 0.f, 0.f); vv = kv;
            }
            *(float4*)&ks[r * KST + c] = kv;
            *(float4*)&vs[r * VST + c] = vv;
        }
        __syncthreads();

        // S = Q K^T  (B-frag: b0 = K[key = nf*8+g][d = kk*8+tg])
        float sacc[8][4];
        #pragma unroll
        for (int nf = 0; nf < 8; nf++)
            #pragma unroll
            for (int r = 0; r < 4; r++) sacc[nf][r] = 0.0f;
        #pragma unroll
        for (int kk = 0; kk < 8; kk++) {
            uint32_t bf[8][2];
            #pragma unroll
            for (int nf = 0; nf < 8; nf++) {
                const float* p = &ks[(nf * 8 + g) * KST + kk * 8 + tg];
                bf[nf][0] = __float_as_uint(p[0]);
                bf[nf][1] = __float_as_uint(p[4]);
            }
            #pragma unroll
            for (int nf = 0; nf < 8; nf++)
                mma_tf32(sacc[nf], qf[kk], bf[nf]);
        }

        // bias + key mask
        float mx0 = -CUDART_INF_F, mx1 = -CUDART_INF_F;
        #pragma unroll
        for (int nf = 0; nf < 8; nf++) {
            int col = j0 + nf * 8 + 2 * tg;
            if (r0 < SS) {
                if (col < SS)     sacc[nf][0] += __ldg(&biasg[(size_t)r0 * SS + col]);
                if (col + 1 < SS) sacc[nf][1] += __ldg(&biasg[(size_t)r0 * SS + col + 1]);
            }
            if (r1 < SS) {
                if (col < SS)     sacc[nf][2] += __ldg(&biasg[(size_t)r1 * SS + col]);
                if (col + 1 < SS) sacc[nf][3] += __ldg(&biasg[(size_t)r1 * SS + col + 1]);
            }
            if (col >= SS)     { sacc[nf][0] = -1e30f; sacc[nf][2] = -1e30f; }
            if (col + 1 >= SS) { sacc[nf][1] = -1e30f; sacc[nf][3] = -1e30f; }
            mx0 = fmaxf(mx0, fmaxf(sacc[nf][0], sacc[nf][1]));
            mx1 = fmaxf(mx1, fmaxf(sacc[nf][2], sacc[nf][3]));
        }
        mx0 = fmaxf(mx0, __shfl_xor_sync(0xffffffffu, mx0, 1));
        mx0 = fmaxf(mx0, __shfl_xor_sync(0xffffffffu, mx0, 2));
        mx1 = fmaxf(mx1, __shfl_xor_sync(0xffffffffu, mx1, 1));
        mx1 = fmaxf(mx1, __shfl_xor_sync(0xffffffffu, mx1, 2));

        float mn0 = fmaxf(m0r, mx0), mn1 = fmaxf(m1r, mx1);
        float corr0 = __expf(m0r - mn0), corr1 = __expf(m1r - mn1);
        m0r = mn0; m1r = mn1;

        float rs0 = 0.0f, rs1 = 0.0f;
        float* pw0 = &ps[(wq * 16 + g) * KST + 2 * tg];
        float* pw1 = pw0 + 8 * KST;
        #pragma unroll
        for (int nf = 0; nf < 8; nf++) {
            float p0 = __expf(sacc[nf][0] - mn0);
            float p1 = __expf(sacc[nf][1] - mn0);
            float p2 = __expf(sacc[nf][2] - mn1);
            float p3 = __expf(sacc[nf][3] - mn1);
            rs0 += p0 + p1; rs1 += p2 + p3;
            float2 w0, w1;
            w0.x = __uint_as_float(tf32r(p0)); w0.y = __uint_as_float(tf32r(p1));
            w1.x = __uint_as_float(tf32r(p2)); w1.y = __uint_as_float(tf32r(p3));
            *(float2*)&pw0[nf * 8] = w0;
            *(float2*)&pw1[nf * 8] = w1;
        }
        rs0 += __shfl_xor_sync(0xffffffffu, rs0, 1);
        rs0 += __shfl_xor_sync(0xffffffffu, rs0, 2);
        rs1 += __shfl_xor_sync(0xffffffffu, rs1, 1);
        rs1 += __shfl_xor_sync(0xffffffffu, rs1, 2);
        l0r = l0r * corr0 + rs0;
        l1r = l1r * corr1 + rs1;
        #pragma unroll
        for (int nf = 0; nf < 8; nf++) {
            oacc[nf][0] *= corr0; oacc[nf][1] *= corr0;
            oacc[nf][2] *= corr1; oacc[nf][3] *= corr1;
        }
        __syncwarp();

        // O += P V  (A-frag from ps; B-frag: b0 = V[key = kk*8+tg][d = nf*8+g])
        #pragma unroll
        for (int kk = 0; kk < 8; kk++) {
            uint32_t af[4];
            const float* pp = &ps[(wq * 16 + g) * KST + kk * 8 + tg];
            af[0] = __float_as_uint(pp[0]);
            af[2] = __float_as_uint(pp[4]);
            af[1] = __float_as_uint(pp[8 * KST]);
            af[3] = __float_as_uint(pp[8 * KST + 4]);
            const float* vb0 = &vs[(kk * 8 + tg) * VST + g];
            const float* vb1 = vb0 + 4 * VST;
            #pragma unroll
            for (int nf = 0; nf < 8; nf++) {
                uint32_t bf[2];
                bf[0] = __float_as_uint(vb0[nf * 8]);
                bf[1] = __float_as_uint(vb1[nf * 8]);
                mma_tf32(oacc[nf], af, bf);
            }
        }
        __syncwarp();   // protect ps before next tile's rewrite
    }

    // normalize + write
    float inv0 = 1.0f / l0r, inv1 = 1.0f / l1r;
    #pragma unroll
    for (int nf = 0; nf < 8; nf++) {
        int col = h * HD + nf * 8 + 2 * tg;
        if (r0 < SS) {
            float2 v = make_float2(oacc[nf][0] * inv0, oacc[nf][1] * inv0);
            *(float2*)&out[((size_t)b * SS + r0) * DD + col] = v;
        }
        if (r1 < SS) {
            float2 v = make_float2(oacc[nf][2] * inv1, oacc[nf][3] * inv1);
            *(float2*)&out[((size_t)b * SS + r1) * DD + col] = v;
        }
    }
}

// ---------------------------------------------------------------------------
extern "C" void kernel_launch(void* const* d_in, const int* in_sizes, int n_in,
                              void* d_out, int out_size)
{
    const float* X     = (const float*)d_in[0];
    const float* Wq    = (const float*)d_in[1];
    const float* bq    = (const float*)d_in[2];
    const float* Wk    = (const float*)d_in[3];
    const float* Wv    = (const float*)d_in[4];
    const float* bv    = (const float*)d_in[5];
    const float* table = (const float*)d_in[6];
    const int*   idx   = (const int*)d_in[7];
    float* out = (float*)d_out;

    cudaFuncSetAttribute(proj_mma_kernel, cudaFuncAttributeMaxDynamicSharedMemorySize, (int)PROJ_SMEM);
    cudaFuncSetAttribute(attn_kernel, cudaFuncAttributeMaxDynamicSharedMemorySize, (int)ATTN_SMEM);

    bias_kernel<<<(SS * SS + 255) / 256, 256>>>(table, idx);
    transpose_w<<<dim3(DD/32, DD/32, 3), dim3(32, 8)>>>(Wq, Wk, Wv);
    proj_mma_kernel<<<dim3((MTOT + BM - 1) / BM, DD / BN, 3), 256, PROJ_SMEM>>>(X, bq, bv);
    attn_kernel<<<dim3(10, SB * HH), 128, ATTN_SMEM>>>(out);
}

// round 10
// speedup vs baseline: 3.3049x; 1.4651x over previous
#include <cuda_runtime.h>
#include <math_constants.h>
#include <cstdint>

#define SB 16
#define SS 577
#define DD 768
#define HH 12
#define HD 64
#define MTOT (SB*SS)
#define BST 580          // padded bias row stride (580*4 % 16 == 0)

// projection GEMM tiling
#define BM 128
#define BN 128
#define BK 32
#define NKC (DD/BK)      // 24
#define ASTR 36          // padded smem row stride (floats)
#define STG_FLOATS ((BM+BN)*ASTR)          // 9216
#define STG_BYTES  (STG_FLOATS*4u)         // 36864
#define PROJ_SMEM  (3u*STG_BYTES)          // 110592

// attention tiling
#define KST 68           // K and P/bias smem stride
#define VST 72           // V smem stride
#define ATTN_SMEM ((64*KST + 64*VST + 64*KST) * 4)   // 53248 B

__device__ float g_q[(size_t)SB*HH*SS*HD];
__device__ float g_k[(size_t)SB*HH*SS*HD];
__device__ float g_v[(size_t)SB*HH*SS*HD];
__device__ float g_xr[(size_t)MTOT*DD];
__device__ float g_wt[(size_t)3*DD*DD];
__device__ float g_bias[(size_t)HH*SS*BST];

__device__ __forceinline__ uint32_t tf32r(float x){
    uint32_t o; asm("cvt.rna.tf32.f32 %0, %1;" : "=r"(o) : "f"(x));
    return o;
}
__device__ __forceinline__ uint32_t smem_u32(const void* p){
    uint32_t a;
    asm("{ .reg .u64 t; cvta.to.shared.u64 t, %1; cvt.u32.u64 %0, t; }" : "=r"(a) : "l"(p));
    return a;
}
__device__ __forceinline__ void cpa16(uint32_t dst, const float* src, bool valid){
    int sz = valid ? 16 : 0;
    asm volatile("cp.async.cg.shared.global [%0], [%1], 16, %2;" :: "r"(dst), "l"(src), "r"(sz));
}
__device__ __forceinline__ void mma_tf32(float* c, const uint32_t* a, const uint32_t* b){
    asm volatile(
        "mma.sync.aligned.m16n8k8.row.col.f32.tf32.tf32.f32 "
        "{%0,%1,%2,%3}, {%4,%5,%6,%7}, {%8,%9}, {%0,%1,%2,%3};"
        : "+f"(c[0]), "+f"(c[1]), "+f"(c[2]), "+f"(c[3])
        : "r"(a[0]), "r"(a[1]), "r"(a[2]), "r"(a[3]), "r"(b[0]), "r"(b[1]));
}

// ---------------- 1) bias gather (padded rows) ----------------
__global__ __launch_bounds__(256) void bias_kernel(const float* __restrict__ table,
                                                   const int* __restrict__ idx)
{
    int e = blockIdx.x * 256 + threadIdx.x;
    if (e >= SS * SS) return;
    int q = e / SS, k = e - q * SS;
    int i = idx[e];
    #pragma unroll
    for (int h = 0; h < HH; h++)
        g_bias[((size_t)h * SS + q) * BST + k] = table[i * HH + h];
}

// ---------------- 1b) pre-round X to tf32 ----------------
__global__ __launch_bounds__(256) void xround_kernel(const float* __restrict__ X)
{
    size_t i = ((size_t)blockIdx.x * 256 + threadIdx.x) * 4;
    if (i < (size_t)MTOT * DD) {
        float4 v = *(const float4*)&X[i];
        v.x = __uint_as_float(tf32r(v.x)); v.y = __uint_as_float(tf32r(v.y));
        v.z = __uint_as_float(tf32r(v.z)); v.w = __uint_as_float(tf32r(v.w));
        *(float4*)&g_xr[i] = v;
    }
}

// ---------------- 2) weight transpose (+ tf32 round) ----------------
__global__ void transpose_w(const float* __restrict__ Wq,
                            const float* __restrict__ Wk,
                            const float* __restrict__ Wv)
{
    __shared__ float t[32][33];
    int g = blockIdx.z;
    const float* W = (g == 0) ? Wq : (g == 1) ? Wk : Wv;
    int k0 = blockIdx.x * 32, n0 = blockIdx.y * 32;
    int tx = threadIdx.x, ty = threadIdx.y;
    #pragma unroll
    for (int i = 0; i < 32; i += 8)
        t[ty + i][tx] = W[(size_t)(k0 + ty + i) * DD + n0 + tx];
    __syncthreads();
    #pragma unroll
    for (int i = 0; i < 32; i += 8)
        g_wt[(size_t)g * DD * DD + (size_t)(n0 + ty + i) * DD + k0 + tx] =
            __uint_as_float(tf32r(t[tx][ty + i]));
}

// ---------------- 3) projection: mma.sync tf32 + cp.async 3-stage ----------------
__global__ __launch_bounds__(256) void proj_mma_kernel(
    const float* __restrict__ bq, const float* __restrict__ bv)
{
    extern __shared__ float smf[];
    const uint32_t s32 = smem_u32(smf);

    const int tid = threadIdx.x;
    const int wid = tid >> 5, lane = tid & 31;
    const int wm = (wid >> 2) * 64;
    const int wn = (wid & 3) * 32;
    const int g = lane >> 2, tg = lane & 3;

    const int m0 = blockIdx.x * BM;
    const int n0 = blockIdx.y * BN;
    const int which = blockIdx.z;
    const float* Wt   = g_wt + (size_t)which * DD * DD;
    float* out        = (which == 0) ? g_q : (which == 1) ? g_k : g_v;
    const float* badd = (which == 0) ? bq : (which == 2) ? bv : nullptr;
    const float scl   = (which == 0) ? 0.125f : 1.0f;

    const int lr  = tid >> 3;          // 0..31 used via u
    (void)lr;

    #define ISSUE_STAGE(kc, stg)                                                     \
    {                                                                                \
        int kb = (kc) * BK;                                                          \
        uint32_t ab = s32 + (stg) * STG_BYTES;                                       \
        uint32_t bb = ab + BM * ASTR * 4u;                                           \
        _Pragma("unroll")                                                            \
        for (int i = 0; i < 4; i++) {                                                \
            int u = tid + i * 256;                                                   \
            int r = u >> 3, c4 = (u & 7) << 2;                                       \
            cpa16(ab + (uint32_t)(r * ASTR + c4) * 4u,                               \
                  &g_xr[(size_t)(m0 + r) * DD + kb + c4], (m0 + r) < MTOT);          \
            cpa16(bb + (uint32_t)(r * ASTR + c4) * 4u,                               \
                  &Wt[(size_t)(n0 + r) * DD + kb + c4], true);                       \
        }                                                                            \
    }

    // prologue: 3 stages in flight
    ISSUE_STAGE(0, 0); asm volatile("cp.async.commit_group;");
    ISSUE_STAGE(1, 1); asm volatile("cp.async.commit_group;");
    ISSUE_STAGE(2, 2); asm volatile("cp.async.commit_group;");

    float acc[4][4][4] = {};

    for (int kc = 0; kc < NKC; kc++) {
        const int stg = kc % 3;
        asm volatile("cp.async.wait_group 2;");
        __syncthreads();

        const float* ab = smf + stg * STG_FLOATS;
        const float* bb = ab + BM * ASTR;
        #pragma unroll
        for (int ks = 0; ks < 4; ks++) {
            const int k8 = ks * 8;
            uint32_t af[4][4], bf[4][2];
            #pragma unroll
            for (int mf = 0; mf < 4; mf++) {
                const float* p = ab + (wm + mf * 16 + g) * ASTR + k8 + tg;
                af[mf][0] = __float_as_uint(p[0]);
                af[mf][2] = __float_as_uint(p[4]);
                af[mf][1] = __float_as_uint(p[8 * ASTR]);
                af[mf][3] = __float_as_uint(p[8 * ASTR + 4]);
            }
            #pragma unroll
            for (int nf = 0; nf < 4; nf++) {
                const float* p = bb + (wn + nf * 8 + g) * ASTR + k8 + tg;
                bf[nf][0] = __float_as_uint(p[0]);
                bf[nf][1] = __float_as_uint(p[4]);
            }
            #pragma unroll
            for (int mf = 0; mf < 4; mf++)
                #pragma unroll
                for (int nf = 0; nf < 4; nf++)
                    mma_tf32(acc[mf][nf], af[mf], bf[nf]);
        }
        __syncthreads();
        if (kc + 3 < NKC) ISSUE_STAGE(kc + 3, stg);
        asm volatile("cp.async.commit_group;");
    }

    // epilogue: tf32-rounded stores into [b,h,s,64]
    #pragma unroll
    for (int mf = 0; mf < 4; mf++) {
        #pragma unroll
        for (int half = 0; half < 2; half++) {
            int m = m0 + wm + mf * 16 + g + half * 8;
            if (m >= MTOT) continue;
            int b = m / SS, s = m - b * SS;
            #pragma unroll
            for (int nf = 0; nf < 4; nf++) {
                int n = n0 + wn + nf * 8 + tg * 2;
                int h = n >> 6, d = n & 63;
                float c0 = acc[mf][nf][half * 2 + 0];
                float c1 = acc[mf][nf][half * 2 + 1];
                if (badd) { c0 += badd[n]; c1 += badd[n + 1]; }
                float2 v;
                v.x = __uint_as_float(tf32r(c0 * scl));
                v.y = __uint_as_float(tf32r(c1 * scl));
                *(float2*)&out[((size_t)(b * HH + h) * SS + s) * HD + d] = v;
            }
        }
    }
}

// ---------------- 4) flash attention via mma.sync tf32 ----------------
// Block: 64 q-rows, 4 warps (16 rows each). Bias tile staged into the P buffer
// (overlay is safe: each address is read-then-written by the same lane).
__global__ __launch_bounds__(128) void attn_kernel(float* __restrict__ out)
{
    extern __shared__ float sh[];
    float* ks = sh;                    // [64][KST]
    float* vs = ks + 64 * KST;         // [64][VST]
    float* ps = vs + 64 * VST;         // [64][KST]  bias tile, then P tile

    const int tid = threadIdx.x;
    const int wq = tid >> 5;
    const int lane = tid & 31;
    const int g = lane >> 2, tg = lane & 3;
    const int q0 = blockIdx.x * 64;
    const int bh = blockIdx.y;                 // h*16 + b
    const int h = bh >> 4, b = bh & 15;

    const float* qg = g_q + (size_t)(b * HH + h) * SS * HD;
    const float* kg = g_k + (size_t)(b * HH + h) * SS * HD;
    const float* vg = g_v + (size_t)(b * HH + h) * SS * HD;
    const float* biasg = g_bias + (size_t)h * SS * BST;

    const int r0 = q0 + wq * 16 + g;
    const int r1 = r0 + 8;

    // Q fragments — register resident
    uint32_t qf[8][4];
    #pragma unroll
    for (int kk = 0; kk < 8; kk++) {
        int c = kk * 8 + tg;
        qf[kk][0] = (r0 < SS) ? __float_as_uint(qg[(size_t)r0 * HD + c])     : 0u;
        qf[kk][1] = (r1 < SS) ? __float_as_uint(qg[(size_t)r1 * HD + c])     : 0u;
        qf[kk][2] = (r0 < SS) ? __float_as_uint(qg[(size_t)r0 * HD + c + 4]) : 0u;
        qf[kk][3] = (r1 < SS) ? __float_as_uint(qg[(size_t)r1 * HD + c + 4]) : 0u;
    }

    float oacc[8][4];
    #pragma unroll
    for (int nf = 0; nf < 8; nf++)
        #pragma unroll
        for (int r = 0; r < 4; r++) oacc[nf][r] = 0.0f;
    float m0r = -CUDART_INF_F, m1r = -CUDART_INF_F, l0r = 0.0f, l1r = 0.0f;

    #pragma unroll 1
    for (int jt = 0; jt < 10; jt++) {
        const int j0 = jt * 64;
        __syncthreads();
        // stage K, V, and bias tiles (coalesced)
        #pragma unroll
        for (int i = 0; i < 8; i++) {
            int u = tid + i * 128;
            int r = u >> 4, c = (u & 15) << 2;
            int srow = j0 + r;
            float4 kv, vv;
            if (srow < SS) {
                kv = *(const float4*)&kg[(size_t)srow * HD + c];
                vv = *(const float4*)&vg[(size_t)srow * HD + c];
            } else {
                kv = make_float4(0.f, 0.f, 0.f, 0.f); vv = kv;
            }
            *(float4*)&ks[r * KST + c] = kv;
            *(float4*)&vs[r * VST + c] = vv;
            // bias tile: rows = q0+r (clamped), cols = j0+c.. (float4 valid iff j0+c < SS)
            int brow = q0 + r; if (brow >= SS) brow = SS - 1;
            float4 bv4 = (j0 + c < SS) ? *(const float4*)&biasg[(size_t)brow * BST + j0 + c]
                                       : make_float4(0.f, 0.f, 0.f, 0.f);
            *(float4*)&ps[r * KST + c] = bv4;
        }
        __syncthreads();

        // S = Q K^T
        float sacc[8][4];
        #pragma unroll
        for (int nf = 0; nf < 8; nf++)
            #pragma unroll
            for (int r = 0; r < 4; r++) sacc[nf][r] = 0.0f;
        #pragma unroll
        for (int kk = 0; kk < 8; kk++) {
            uint32_t bf[8][2];
            #pragma unroll
            for (int nf = 0; nf < 8; nf++) {
                const float* p = &ks[(nf * 8 + g) * KST + kk * 8 + tg];
                bf[nf][0] = __float_as_uint(p[0]);
                bf[nf][1] = __float_as_uint(p[4]);
            }
            #pragma unroll
            for (int nf = 0; nf < 8; nf++)
                mma_tf32(sacc[nf], qf[kk], bf[nf]);
        }

        // bias add from smem + key mask + row max
        const float* bb0 = &ps[(wq * 16 + g) * KST + 2 * tg];
        const float* bb1 = bb0 + 8 * KST;
        float mx0 = -CUDART_INF_F, mx1 = -CUDART_INF_F;
        #pragma unroll
        for (int nf = 0; nf < 8; nf++) {
            int col = j0 + nf * 8 + 2 * tg;
            float2 b0 = *(const float2*)&bb0[nf * 8];
            float2 b1 = *(const float2*)&bb1[nf * 8];
            sacc[nf][0] += b0.x; sacc[nf][1] += b0.y;
            sacc[nf][2] += b1.x; sacc[nf][3] += b1.y;
            if (col >= SS)     { sacc[nf][0] = -1e30f; sacc[nf][2] = -1e30f; }
            if (col + 1 >= SS) { sacc[nf][1] = -1e30f; sacc[nf][3] = -1e30f; }
            mx0 = fmaxf(mx0, fmaxf(sacc[nf][0], sacc[nf][1]));
            mx1 = fmaxf(mx1, fmaxf(sacc[nf][2], sacc[nf][3]));
        }
        mx0 = fmaxf(mx0, __shfl_xor_sync(0xffffffffu, mx0, 1));
        mx0 = fmaxf(mx0, __shfl_xor_sync(0xffffffffu, mx0, 2));
        mx1 = fmaxf(mx1, __shfl_xor_sync(0xffffffffu, mx1, 1));
        mx1 = fmaxf(mx1, __shfl_xor_sync(0xffffffffu, mx1, 2));

        float mn0 = fmaxf(m0r, mx0), mn1 = fmaxf(m1r, mx1);
        float corr0 = __expf(m0r - mn0), corr1 = __expf(m1r - mn1);
        m0r = mn0; m1r = mn1;

        float rs0 = 0.0f, rs1 = 0.0f;
        float* pw0 = &ps[(wq * 16 + g) * KST + 2 * tg];
        float* pw1 = pw0 + 8 * KST;
        #pragma unroll
        for (int nf = 0; nf < 8; nf++) {
            float p0 = __expf(sacc[nf][0] - mn0);
            float p1 = __expf(sacc[nf][1] - mn0);
            float p2 = __expf(sacc[nf][2] - mn1);
            float p3 = __expf(sacc[nf][3] - mn1);
            rs0 += p0 + p1; rs1 += p2 + p3;
            float2 w0, w1;
            w0.x = __uint_as_float(tf32r(p0)); w0.y = __uint_as_float(tf32r(p1));
            w1.x = __uint_as_float(tf32r(p2)); w1.y = __uint_as_float(tf32r(p3));
            *(float2*)&pw0[nf * 8] = w0;
            *(float2*)&pw1[nf * 8] = w1;
        }
        rs0 += __shfl_xor_sync(0xffffffffu, rs0, 1);
        rs0 += __shfl_xor_sync(0xffffffffu, rs0, 2);
        rs1 += __shfl_xor_sync(0xffffffffu, rs1, 1);
        rs1 += __shfl_xor_sync(0xffffffffu, rs1, 2);
        l0r = l0r * corr0 + rs0;
        l1r = l1r * corr1 + rs1;
        #pragma unroll
        for (int nf = 0; nf < 8; nf++) {
            oacc[nf][0] *= corr0; oacc[nf][1] *= corr0;
            oacc[nf][2] *= corr1; oacc[nf][3] *= corr1;
        }
        __syncwarp();

        // O += P V
        #pragma unroll
        for (int kk = 0; kk < 8; kk++) {
            uint32_t af[4];
            const float* pp = &ps[(wq * 16 + g) * KST + kk * 8 + tg];
            af[0] = __float_as_uint(pp[0]);
            af[2] = __float_as_uint(pp[4]);
            af[1] = __float_as_uint(pp[8 * KST]);
            af[3] = __float_as_uint(pp[8 * KST + 4]);
            const float* vb0 = &vs[(kk * 8 + tg) * VST + g];
            const float* vb1 = vb0 + 4 * VST;
            #pragma unroll
            for (int nf = 0; nf < 8; nf++) {
                uint32_t bf[2];
                bf[0] = __float_as_uint(vb0[nf * 8]);
                bf[1] = __float_as_uint(vb1[nf * 8]);
                mma_tf32(oacc[nf], af, bf);
            }
        }
        __syncwarp();
    }

    float inv0 = 1.0f / l0r, inv1 = 1.0f / l1r;
    #pragma unroll
    for (int nf = 0; nf < 8; nf++) {
        int col = h * HD + nf * 8 + 2 * tg;
        if (r0 < SS) {
            float2 v = make_float2(oacc[nf][0] * inv0, oacc[nf][1] * inv0);
            *(float2*)&out[((size_t)b * SS + r0) * DD + col] = v;
        }
        if (r1 < SS) {
            float2 v = make_float2(oacc[nf][2] * inv1, oacc[nf][3] * inv1);
            *(float2*)&out[((size_t)b * SS + r1) * DD + col] = v;
        }
    }
}

// ---------------------------------------------------------------------------
extern "C" void kernel_launch(void* const* d_in, const int* in_sizes, int n_in,
                              void* d_out, int out_size)
{
    const float* X     = (const float*)d_in[0];
    const float* Wq    = (const float*)d_in[1];
    const float* bq    = (const float*)d_in[2];
    const float* Wk    = (const float*)d_in[3];
    const float* Wv    = (const float*)d_in[4];
    const float* bv    = (const float*)d_in[5];
    const float* table = (const float*)d_in[6];
    const int*   idx   = (const int*)d_in[7];
    float* out = (float*)d_out;

    cudaFuncSetAttribute(proj_mma_kernel, cudaFuncAttributeMaxDynamicSharedMemorySize, (int)PROJ_SMEM);
    cudaFuncSetAttribute(attn_kernel, cudaFuncAttributeMaxDynamicSharedMemorySize, (int)ATTN_SMEM);

    bias_kernel<<<(SS * SS + 255) / 256, 256>>>(table, idx);
    xround_kernel<<<(MTOT * DD / 4 + 255) / 256, 256>>>(X);
    transpose_w<<<dim3(DD/32, DD/32, 3), dim3(32, 8)>>>(Wq, Wk, Wv);
    proj_mma_kernel<<<dim3((MTOT + BM - 1) / BM, DD / BN, 3), 256, PROJ_SMEM>>>(bq, bv);
    attn_kernel<<<dim3(10, SB * HH), 128, ATTN_SMEM>>>(out);
}

// round 12
// speedup vs baseline: 3.5097x; 1.0620x over previous
#include <cuda_runtime.h>
#include <math_constants.h>
#include <cstdint>

#define SB 16
#define SS 577
#define DD 768
#define HH 12
#define HD 64
#define MTOT (SB*SS)
#define BST 580          // padded bias row stride

// projection GEMM tiling
#define BM 128
#define BN 128
#define BK 32
#define NKC (DD/BK)      // 24
#define ASTR 36          // padded smem row stride (floats) — bank stride 4
#define STG_FLOATS ((BM+BN)*ASTR)          // 9216
#define STG_BYTES  (STG_FLOATS*4u)         // 36864
#define PROJ_SMEM  (3u*STG_BYTES)          // 110592

// attention tiling
#define KST 68           // K and P/bias smem stride — bank stride 4
#define VST 72           // V smem stride — bank stride 8 (scalar LDS pattern cf)
#define ATTN_SMEM ((64*KST + 64*VST + 64*KST) * 4)   // 53248 B

__device__ float g_q[(size_t)SB*HH*SS*HD];
__device__ float g_k[(size_t)SB*HH*SS*HD];
__device__ float g_v[(size_t)SB*HH*SS*HD];
__device__ float g_xr[(size_t)MTOT*DD];
__device__ float g_wt[(size_t)3*DD*DD];
__device__ float g_bias[(size_t)HH*SS*BST];

__device__ __forceinline__ uint32_t tf32r(float x){
    uint32_t o; asm("cvt.rna.tf32.f32 %0, %1;" : "=r"(o) : "f"(x));
    return o;
}
__device__ __forceinline__ uint32_t smem_u32(const void* p){
    uint32_t a;
    asm("{ .reg .u64 t; cvta.to.shared.u64 t, %1; cvt.u32.u64 %0, t; }" : "=r"(a) : "l"(p));
    return a;
}
__device__ __forceinline__ void cpa16(uint32_t dst, const float* src, bool valid){
    int sz = valid ? 16 : 0;
    asm volatile("cp.async.cg.shared.global [%0], [%1], 16, %2;" :: "r"(dst), "l"(src), "r"(sz));
}
__device__ __forceinline__ void ldsm4(uint32_t* r, uint32_t addr){
    asm volatile("ldmatrix.sync.aligned.m8n8.x4.shared.b16 {%0,%1,%2,%3}, [%4];"
        : "=r"(r[0]), "=r"(r[1]), "=r"(r[2]), "=r"(r[3]) : "r"(addr));
}
__device__ __forceinline__ void mma_tf32(float* c, const uint32_t* a, const uint32_t* b){
    asm volatile(
        "mma.sync.aligned.m16n8k8.row.col.f32.tf32.tf32.f32 "
        "{%0,%1,%2,%3}, {%4,%5,%6,%7}, {%8,%9}, {%0,%1,%2,%3};"
        : "+f"(c[0]), "+f"(c[1]), "+f"(c[2]), "+f"(c[3])
        : "r"(a[0]), "r"(a[1]), "r"(a[2]), "r"(a[3]), "r"(b[0]), "r"(b[1]));
}

// ---------------- 1) bias gather (padded rows) ----------------
__global__ __launch_bounds__(256) void bias_kernel(const float* __restrict__ table,
                                                   const int* __restrict__ idx)
{
    int e = blockIdx.x * 256 + threadIdx.x;
    if (e >= SS * SS) return;
    int q = e / SS, k = e - q * SS;
    int i = idx[e];
    #pragma unroll
    for (int h = 0; h < HH; h++)
        g_bias[((size_t)h * SS + q) * BST + k] = table[i * HH + h];
}

// ---------------- 1b) pre-round X to tf32 ----------------
__global__ __launch_bounds__(256) void xround_kernel(const float* __restrict__ X)
{
    size_t i = ((size_t)blockIdx.x * 256 + threadIdx.x) * 4;
    if (i < (size_t)MTOT * DD) {
        float4 v = *(const float4*)&X[i];
        v.x = __uint_as_float(tf32r(v.x)); v.y = __uint_as_float(tf32r(v.y));
        v.z = __uint_as_float(tf32r(v.z)); v.w = __uint_as_float(tf32r(v.w));
        *(float4*)&g_xr[i] = v;
    }
}

// ---------------- 2) weight transpose (+ tf32 round) ----------------
__global__ void transpose_w(const float* __restrict__ Wq,
                            const float* __restrict__ Wk,
                            const float* __restrict__ Wv)
{
    __shared__ float t[32][33];
    int g = blockIdx.z;
    const float* W = (g == 0) ? Wq : (g == 1) ? Wk : Wv;
    int k0 = blockIdx.x * 32, n0 = blockIdx.y * 32;
    int tx = threadIdx.x, ty = threadIdx.y;
    #pragma unroll
    for (int i = 0; i < 32; i += 8)
        t[ty + i][tx] = W[(size_t)(k0 + ty + i) * DD + n0 + tx];
    __syncthreads();
    #pragma unroll
    for (int i = 0; i < 32; i += 8)
        g_wt[(size_t)g * DD * DD + (size_t)(n0 + ty + i) * DD + k0 + tx] =
            __uint_as_float(tf32r(t[tx][ty + i]));
}

// ---------------- 3) projection: mma.sync tf32 + cp.async + ldmatrix ----------------
__global__ __launch_bounds__(256) void proj_mma_kernel(
    const float* __restrict__ bq, const float* __restrict__ bv)
{
    extern __shared__ float smf[];
    const uint32_t s32 = smem_u32(smf);

    const int tid = threadIdx.x;
    const int wid = tid >> 5, lane = tid & 31;
    const int wm = (wid >> 2) * 64;
    const int wn = (wid & 3) * 32;
    const int g = lane >> 2, tg = lane & 3;

    const int m0 = blockIdx.x * BM;
    const int n0 = blockIdx.y * BN;
    const int which = blockIdx.z;
    const float* Wt   = g_wt + (size_t)which * DD * DD;
    float* out        = (which == 0) ? g_q : (which == 1) ? g_k : g_v;
    const float* badd = (which == 0) ? bq : (which == 2) ? bv : nullptr;
    const float scl   = (which == 0) ? 0.125f : 1.0f;

    // ldmatrix per-lane address components
    // A: m0=rows0-7/klo, m1=rows8-15/klo, m2=rows0-7/khi, m3=rows8-15/khi
    const uint32_t a_row  = wm + (lane & 15);
    const uint32_t a_ksel = (uint32_t)(lane >> 4) << 2;             // 0 or 4
    const uint32_t aoff = (a_row * ASTR + a_ksel) * 4u;
    // B: m0=nrows0-7/klo, m1=nrows0-7/khi, m2=nrows8-15/klo, m3=nrows8-15/khi
    const uint32_t b_row  = wn + (lane & 7) + ((lane >> 4) << 3);
    const uint32_t b_ksel = (uint32_t)((lane >> 3) & 1) << 2;       // 0 or 4
    const uint32_t boff = (uint32_t)(BM * ASTR) * 4u + (b_row * ASTR + b_ksel) * 4u;

    #define ISSUE_STAGE(kc, stg)                                                     \
    {                                                                                \
        int kb = (kc) * BK;                                                          \
        uint32_t ab = s32 + (stg) * STG_BYTES;                                       \
        uint32_t bb = ab + BM * ASTR * 4u;                                           \
        _Pragma("unroll")                                                            \
        for (int i = 0; i < 4; i++) {                                                \
            int u = tid + i * 256;                                                   \
            int r = u >> 3, c4 = (u & 7) << 2;                                       \
            cpa16(ab + (uint32_t)(r * ASTR + c4) * 4u,                               \
                  &g_xr[(size_t)(m0 + r) * DD + kb + c4], (m0 + r) < MTOT);          \
            cpa16(bb + (uint32_t)(r * ASTR + c4) * 4u,                               \
                  &Wt[(size_t)(n0 + r) * DD + kb + c4], true);                       \
        }                                                                            \
    }

    ISSUE_STAGE(0, 0); asm volatile("cp.async.commit_group;");
    ISSUE_STAGE(1, 1); asm volatile("cp.async.commit_group;");
    ISSUE_STAGE(2, 2); asm volatile("cp.async.commit_group;");

    float acc[4][4][4] = {};

    for (int kc = 0; kc < NKC; kc++) {
        const int stg = kc % 3;
        asm volatile("cp.async.wait_group 2;");
        __syncthreads();

        const uint32_t abase = s32 + stg * STG_BYTES + aoff;
        const uint32_t bbase = s32 + stg * STG_BYTES + boff;
        #pragma unroll
        for (int ks = 0; ks < 4; ks++) {
            const uint32_t k8b = (uint32_t)(ks * 8) * 4u;
            uint32_t af[4][4], bf[4][2];
            #pragma unroll
            for (int mf = 0; mf < 4; mf++)
                ldsm4(af[mf], abase + (uint32_t)(mf * 16 * ASTR) * 4u + k8b);
            #pragma unroll
            for (int p = 0; p < 2; p++)
                ldsm4(&bf[2 * p][0], bbase + (uint32_t)(p * 16 * ASTR) * 4u + k8b);
            #pragma unroll
            for (int mf = 0; mf < 4; mf++)
                #pragma unroll
                for (int nf = 0; nf < 4; nf++)
                    mma_tf32(acc[mf][nf], af[mf], bf[nf]);
        }
        __syncthreads();
        if (kc + 3 < NKC) ISSUE_STAGE(kc + 3, stg);
        asm volatile("cp.async.commit_group;");
    }

    // epilogue: tf32-rounded stores into [b,h,s,64]
    #pragma unroll
    for (int mf = 0; mf < 4; mf++) {
        #pragma unroll
        for (int half = 0; half < 2; half++) {
            int m = m0 + wm + mf * 16 + g + half * 8;
            if (m >= MTOT) continue;
            int b = m / SS, s = m - b * SS;
            #pragma unroll
            for (int nf = 0; nf < 4; nf++) {
                int n = n0 + wn + nf * 8 + tg * 2;
                int h = n >> 6, d = n & 63;
                float c0 = acc[mf][nf][half * 2 + 0];
                float c1 = acc[mf][nf][half * 2 + 1];
                if (badd) { c0 += badd[n]; c1 += badd[n + 1]; }
                float2 v;
                v.x = __uint_as_float(tf32r(c0 * scl));
                v.y = __uint_as_float(tf32r(c1 * scl));
                *(float2*)&out[((size_t)(b * HH + h) * SS + s) * HD + d] = v;
            }
        }
    }
}

// ---------------- 4) flash attention: mma.sync tf32 + ldmatrix ----------------
__global__ __launch_bounds__(128) void attn_kernel(float* __restrict__ out)
{
    extern __shared__ float sh[];
    float* ks = sh;                    // [64][KST]
    float* vs = ks + 64 * KST;         // [64][VST]
    float* ps = vs + 64 * VST;         // [64][KST]  bias tile, then P tile
    const uint32_t s32 = smem_u32(sh);
    const uint32_t ks32 = s32;
    const uint32_t ps32 = s32 + (64 * KST + 64 * VST) * 4u;

    const int tid = threadIdx.x;
    const int wq = tid >> 5;
    const int lane = tid & 31;
    const int g = lane >> 2, tg = lane & 3;
    const int q0 = blockIdx.x * 64;
    const int bh = blockIdx.y;                 // h*16 + b
    const int h = bh >> 4, b = bh & 15;

    const float* qg = g_q + (size_t)(b * HH + h) * SS * HD;
    const float* kg = g_k + (size_t)(b * HH + h) * SS * HD;
    const float* vg = g_v + (size_t)(b * HH + h) * SS * HD;
    const float* biasg = g_bias + (size_t)h * SS * BST;

    const int r0 = q0 + wq * 16 + g;
    const int r1 = r0 + 8;

    // ldmatrix lane address components
    const uint32_t kb_row  = (lane & 7) + ((lane >> 4) << 3);            // K B-frags
    const uint32_t kb_ksel = (uint32_t)((lane >> 3) & 1) << 2;
    const uint32_t kfoff = ks32 + (kb_row * KST + kb_ksel) * 4u;
    const uint32_t pa_row  = wq * 16 + (lane & 15);                      // P A-frag
    const uint32_t pa_ksel = (uint32_t)(lane >> 4) << 2;
    const uint32_t pfoff = ps32 + (pa_row * KST + pa_ksel) * 4u;

    // Q fragments — register resident
    uint32_t qf[8][4];
    #pragma unroll
    for (int kk = 0; kk < 8; kk++) {
        int c = kk * 8 + tg;
        qf[kk][0] = (r0 < SS) ? __float_as_uint(qg[(size_t)r0 * HD + c])     : 0u;
        qf[kk][1] = (r1 < SS) ? __float_as_uint(qg[(size_t)r1 * HD + c])     : 0u;
        qf[kk][2] = (r0 < SS) ? __float_as_uint(qg[(size_t)r0 * HD + c + 4]) : 0u;
        qf[kk][3] = (r1 < SS) ? __float_as_uint(qg[(size_t)r1 * HD + c + 4]) : 0u;
    }

    float oacc[8][4];
    #pragma unroll
    for (int nf = 0; nf < 8; nf++)
        #pragma unroll
        for (int r = 0; r < 4; r++) oacc[nf][r] = 0.0f;
    float m0r = -CUDART_INF_F, m1r = -CUDART_INF_F, l0r = 0.0f, l1r = 0.0f;

    #pragma unroll 1
    for (int jt = 0; jt < 10; jt++) {
        const int j0 = jt * 64;
        __syncthreads();
        // stage K, V, and bias tiles (coalesced)
        #pragma unroll
        for (int i = 0; i < 8; i++) {
            int u = tid + i * 128;
            int r = u >> 4, c = (u & 15) << 2;
            int srow = j0 + r;
            float4 kv, vv;
            if (srow < SS) {
                kv = *(const float4*)&kg[(size_t)srow * HD + c];
                vv = *(const float4*)&vg[(size_t)srow * HD + c];
            } else {
                kv = make_float4(0.f, 0.f, 0.f, 0.f); vv = kv;
            }
            *(float4*)&ks[r * KST + c] = kv;
            *(float4*)&vs[r * VST + c] = vv;
            int brow = q0 + r; if (brow >= SS) brow = SS - 1;
            float4 bv4 = (j0 + c < SS) ? *(const float4*)&biasg[(size_t)brow * BST + j0 + c]
                                       : make_float4(0.f, 0.f, 0.f, 0.f);
            *(float4*)&ps[r * KST + c] = bv4;
        }
        __syncthreads();

        // S = Q K^T (K B-frags via ldmatrix)
        float sacc[8][4];
        #pragma unroll
        for (int nf = 0; nf < 8; nf++)
            #pragma unroll
            for (int r = 0; r < 4; r++) sacc[nf][r] = 0.0f;
        #pragma unroll
        for (int kk = 0; kk < 8; kk++) {
            uint32_t bf[8][2];
            #pragma unroll
            for (int p = 0; p < 4; p++)
                ldsm4(&bf[2 * p][0], kfoff + (uint32_t)(p * 16 * KST + kk * 8) * 4u);
            #pragma unroll
            for (int nf = 0; nf < 8; nf++)
                mma_tf32(sacc[nf], qf[kk], bf[nf]);
        }

        // bias add from smem + key mask + row max
        const float* bb0 = &ps[(wq * 16 + g) * KST + 2 * tg];
        const float* bb1 = bb0 + 8 * KST;
        float mx0 = -CUDART_INF_F, mx1 = -CUDART_INF_F;
        #pragma unroll
        for (int nf = 0; nf < 8; nf++) {
            int col = j0 + nf * 8 + 2 * tg;
            float2 b0 = *(const float2*)&bb0[nf * 8];
            float2 b1 = *(const float2*)&bb1[nf * 8];
            sacc[nf][0] += b0.x; sacc[nf][1] += b0.y;
            sacc[nf][2] += b1.x; sacc[nf][3] += b1.y;
            if (col >= SS)     { sacc[nf][0] = -1e30f; sacc[nf][2] = -1e30f; }
            if (col + 1 >= SS) { sacc[nf][1] = -1e30f; sacc[nf][3] = -1e30f; }
            mx0 = fmaxf(mx0, fmaxf(sacc[nf][0], sacc[nf][1]));
            mx1 = fmaxf(mx1, fmaxf(sacc[nf][2], sacc[nf][3]));
        }
        mx0 = fmaxf(mx0, __shfl_xor_sync(0xffffffffu, mx0, 1));
        mx0 = fmaxf(mx0, __shfl_xor_sync(0xffffffffu, mx0, 2));
        mx1 = fmaxf(mx1, __shfl_xor_sync(0xffffffffu, mx1, 1));
        mx1 = fmaxf(mx1, __shfl_xor_sync(0xffffffffu, mx1, 2));

        float mn0 = fmaxf(m0r, mx0), mn1 = fmaxf(m1r, mx1);
        float corr0 = __expf(m0r - mn0), corr1 = __expf(m1r - mn1);
        m0r = mn0; m1r = mn1;

        float rs0 = 0.0f, rs1 = 0.0f;
        float* pw0 = &ps[(wq * 16 + g) * KST + 2 * tg];
        float* pw1 = pw0 + 8 * KST;
        #pragma unroll
        for (int nf = 0; nf < 8; nf++) {
            float p0 = __expf(sacc[nf][0] - mn0);
            float p1 = __expf(sacc[nf][1] - mn0);
            float p2 = __expf(sacc[nf][2] - mn1);
            float p3 = __expf(sacc[nf][3] - mn1);
            rs0 += p0 + p1; rs1 += p2 + p3;
            float2 w0, w1;
            w0.x = __uint_as_float(tf32r(p0)); w0.y = __uint_as_float(tf32r(p1));
            w1.x = __uint_as_float(tf32r(p2)); w1.y = __uint_as_float(tf32r(p3));
            *(float2*)&pw0[nf * 8] = w0;
            *(float2*)&pw1[nf * 8] = w1;
        }
        rs0 += __shfl_xor_sync(0xffffffffu, rs0, 1);
        rs0 += __shfl_xor_sync(0xffffffffu, rs0, 2);
        rs1 += __shfl_xor_sync(0xffffffffu, rs1, 1);
        rs1 += __shfl_xor_sync(0xffffffffu, rs1, 2);
        l0r = l0r * corr0 + rs0;
        l1r = l1r * corr1 + rs1;
        #pragma unroll
        for (int nf = 0; nf < 8; nf++) {
            oacc[nf][0] *= corr0; oacc[nf][1] *= corr0;
            oacc[nf][2] *= corr1; oacc[nf][3] *= corr1;
        }
        __syncwarp();

        // O += P V (P A-frag via ldmatrix; V B-frags scalar, conflict-free)
        #pragma unroll
        for (int kk = 0; kk < 8; kk++) {
            uint32_t af[4];
            ldsm4(af, pfoff + (uint32_t)(kk * 8) * 4u);
            const float* vb0 = &vs[(kk * 8 + tg) * VST + g];
            const float* vb1 = vb0 + 4 * VST;
            #pragma unroll
            for (int nf = 0; nf < 8; nf++) {
                uint32_t bf[2];
                bf[0] = __float_as_uint(vb0[nf * 8]);
                bf[1] = __float_as_uint(vb1[nf * 8]);
                mma_tf32(oacc[nf], af, bf);
            }
        }
        __syncwarp();
    }

    float inv0 = 1.0f / l0r, inv1 = 1.0f / l1r;
    #pragma unroll
    for (int nf = 0; nf < 8; nf++) {
        int col = h * HD + nf * 8 + 2 * tg;
        if (r0 < SS) {
            float2 v = make_float2(oacc[nf][0] * inv0, oacc[nf][1] * inv0);
            *(float2*)&out[((size_t)b * SS + r0) * DD + col] = v;
        }
        if (r1 < SS) {
            float2 v = make_float2(oacc[nf][2] * inv1, oacc[nf][3] * inv1);
            *(float2*)&out[((size_t)b * SS + r1) * DD + col] = v;
        }
    }
}

// ---------------------------------------------------------------------------
extern "C" void kernel_launch(void* const* d_in, const int* in_sizes, int n_in,
                              void* d_out, int out_size)
{
    const float* X     = (const float*)d_in[0];
    const float* Wq    = (const float*)d_in[1];
    const float* bq    = (const float*)d_in[2];
    const float* Wk    = (const float*)d_in[3];
    const float* Wv    = (const float*)d_in[4];
    const float* bv    = (const float*)d_in[5];
    const float* table = (const float*)d_in[6];
    const int*   idx   = (const int*)d_in[7];
    float* out = (float*)d_out;

    cudaFuncSetAttribute(proj_mma_kernel, cudaFuncAttributeMaxDynamicSharedMemorySize, (int)PROJ_SMEM);
    cudaFuncSetAttribute(attn_kernel, cudaFuncAttributeMaxDynamicSharedMemorySize, (int)ATTN_SMEM);

    bias_kernel<<<(SS * SS + 255) / 256, 256>>>(table, idx);
    xround_kernel<<<(MTOT * DD / 4 + 255) / 256, 256>>>(X);
    transpose_w<<<dim3(DD/32, DD/32, 3), dim3(32, 8)>>>(Wq, Wk, Wv);
    proj_mma_kernel<<<dim3((MTOT + BM - 1) / BM, DD / BN, 3), 256, PROJ_SMEM>>>(bq, bv);
    attn_kernel<<<dim3(10, SB * HH), 128, ATTN_SMEM>>>(out);
}